// round 11
// baseline (speedup 1.0000x reference)
#include <cuda_runtime.h>
#include <math.h>

#define Bq 2
#define Lq 5
#define Cq 64
#define Hq 128
#define Wq 256
#define HWq (Hq * Wq)          // 32768
#define NHWq (Lq * Bq * HWq)   // 327680
#define OUTQ (Bq * Cq * HWq)   // 4194304

#define PBLK 1024              // pixel-blocks per batch (32 px each)

// ---------------- scratch (all slots fully overwritten per launch; replay-safe) ----------------
__device__ float g_sum_b[Bq * Cq][PBLK];   // [b*64+c][bx] private per-block pool partials
__device__ float g_max_b[Bq * Cq][PBLK];
__device__ float g_gate[Bq * Cq];
__device__ int   g_cnt_blk[Bq * PBLK];

// 5x5 Gaussian, sigma=1: 1/(2*pi*sigma) * exp(-(dx^2+dy^2)/2)  (NOT normalized, matches ref)
__constant__ float GK[25] = {
    0.0029150243f, 0.0130642333f, 0.0215392793f, 0.0130642333f, 0.0029150243f,
    0.0130642333f, 0.0585498315f, 0.0965323526f, 0.0585498315f, 0.0130642333f,
    0.0215392793f, 0.0965323526f, 0.1591549431f, 0.0965323526f, 0.0215392793f,
    0.0130642333f, 0.0585498315f, 0.0965323526f, 0.0585498315f, 0.0130642333f,
    0.0029150243f, 0.0130642333f, 0.0215392793f, 0.0130642333f, 0.0029150243f
};

__device__ __forceinline__ float fsig(float x) { return 1.0f / (1.0f + __expf(-x)); }

// ============ kernel 1: mask + attention + pooling, fully fused ============
// Block = 32 pixels of one row, 8 warps; warp w owns channels [8w, 8w+8).
// x LDGs issued FIRST; psm->conf->mask work executes inside their latency shadow.
__global__ void __launch_bounds__(256) fuse_kernel(
        const float* __restrict__ x,
        const float* __restrict__ psm,
        const float* __restrict__ inv_delay,
        const float* __restrict__ ew_w,
        const float* __restrict__ ew_b,
        const float* __restrict__ ewc_w,
        const float* __restrict__ ewc_b,
        float* __restrict__ out) {
    __shared__ float s_conf[Lq][5][36];    // agent x 5 rows x (32+4) cols
    __shared__ float s_part[8][Lq][32];
    __shared__ float s_mask[Lq][32];
    __shared__ float s_enw[Lq];
    __shared__ float s_enc[Lq];
    __shared__ int   s_cnt;

    const int b    = blockIdx.y;
    const int bx   = blockIdx.x;           // 0..1023
    const int tid  = threadIdx.x;
    const int lane = tid & 31;
    const int wid  = tid >> 5;
    const int row  = bx >> 3;              // pixel row
    const int c0   = (bx & 7) * 32;        // first pixel column
    const int p    = row * Wq + c0 + lane; // this lane's pixel

    if (tid < Lq)
        s_enc[tid] = tanhf(inv_delay[b * Lq + tid] * ewc_w[0] + ewc_b[0]) + 1.0f;
    else if (tid < 2 * Lq)
        s_enw[tid - Lq] = tanhf(inv_delay[b * Lq + tid - Lq] * ew_w[0] + ew_b[0]) + 1.0f;
    if (tid == 0) s_cnt = 0;
    __syncthreads();

    // ---- issue the 40 long-latency x loads first ----
    const float* xb = x + ((size_t)(b * Lq) * Cq + wid * 8) * HWq + p;
    float xv[8][Lq];
#pragma unroll
    for (int c = 0; c < 8; c++)
#pragma unroll
        for (int l = 0; l < Lq; l++)
            xv[c][l] = xb[((size_t)l * Cq + c) * HWq];

    // ---- conf tile fill (900 elems) in the x-load shadow ----
#pragma unroll
    for (int k = 0; k < 4; k++) {
        int idx = tid + k * 256;
        if (idx < Lq * 5 * 36) {
            int l   = idx / 180;
            int rem = idx - l * 180;
            int r   = rem / 36;
            int cc  = rem - r * 36;
            int h = row + r - 2, w = c0 + cc - 2;
            float v = 0.0f;                               // zero-pad = 'SAME'
            if (h >= 0 && h < Hq && w >= 0 && w < Wq) {
                int n = b * Lq + l;
                int gi = h * Wq + w;
                v = fmaxf(fsig(psm[(size_t)(n * 2 + 0) * HWq + gi]),
                          fsig(psm[(size_t)(n * 2 + 1) * HWq + gi])) * s_enc[l];
            }
            s_conf[l][r][cc] = v;
        }
    }
    __syncthreads();

    // ---- masks: warp w (w<5) handles agent w, lane = pixel ----
    if (wid < Lq) {
        float acc = 0.0f;
#pragma unroll
        for (int dy = 0; dy < 5; dy++)
#pragma unroll
            for (int dx = 0; dx < 5; dx++)
                acc += GK[dy * 5 + dx] * s_conf[wid][dy][lane + dx];
        float m = (acc > 0.01f || wid == 0) ? 1.0f : 0.0f;   // ego always communicates
        s_mask[wid][lane] = m;
        unsigned bal = __ballot_sync(0xffffffffu, m > 0.5f);
        if (lane == 0) atomicAdd(&s_cnt, __popc(bal));
    }

    // ---- partial dots over this warp's 8 channels ----
    float pd[Lq] = {0.f, 0.f, 0.f, 0.f, 0.f};
#pragma unroll
    for (int c = 0; c < 8; c++) {
        float e = xv[c][0];
#pragma unroll
        for (int l = 0; l < Lq; l++) pd[l] += e * xv[c][l];
    }
#pragma unroll
    for (int l = 0; l < Lq; l++) s_part[wid][l][lane] = pd[l];
    __syncthreads();

    if (tid == 0) g_cnt_blk[b * PBLK + bx] = s_cnt;

    float dot[Lq];
#pragma unroll
    for (int l = 0; l < Lq; l++) {
        float t = 0.0f;
#pragma unroll
        for (int w = 0; w < 8; w++) t += s_part[w][l][lane];
        dot[l] = t;
    }

    float s[Lq];
#pragma unroll
    for (int l = 0; l < Lq; l++) s[l] = s_enw[l] * s_mask[l][lane];

    float scv[Lq], mx = -INFINITY;
#pragma unroll
    for (int l = 0; l < Lq; l++) {
        scv[l] = dot[l] * s[0] * s[l] * 0.125f;           // 1/sqrt(64)
        mx = fmaxf(mx, scv[l]);
    }
    float esum = 0.0f;
#pragma unroll
    for (int l = 0; l < Lq; l++) { scv[l] = __expf(scv[l] - mx); esum += scv[l]; }
    float inv = 1.0f / esum;
    float coef[Lq];
#pragma unroll
    for (int l = 0; l < Lq; l++) coef[l] = scv[l] * inv * s[l];

    // ---- output + per-channel pooling (warp-reduce over 32 px, private plain stores) ----
    float* ob = out + ((size_t)b * Cq + wid * 8) * HWq + p;
    float psum[8], pmax[8];
#pragma unroll
    for (int c = 0; c < 8; c++) {
        float f = 0.0f;
#pragma unroll
        for (int l = 0; l < Lq; l++) f += coef[l] * xv[c][l];
        ob[(size_t)c * HWq] = f;
        float ws = f, wm = f;
#pragma unroll
        for (int o = 16; o > 0; o >>= 1) {
            ws += __shfl_xor_sync(0xffffffffu, ws, o);
            wm = fmaxf(wm, __shfl_xor_sync(0xffffffffu, wm, o));
        }
        psum[c] = ws; pmax[c] = wm;
    }
    if (lane == 0) {
        int cb = b * Cq + wid * 8;
#pragma unroll
        for (int c = 0; c < 8; c++) {
            g_sum_b[cb + c][bx] = psum[c];
            g_max_b[cb + c][bx] = pmax[c];
        }
    }
}

// ============ kernel 2: fold private pools + gate MLP + comm_rate (1 block) ============
__global__ void __launch_bounds__(256) reduce_gate_kernel(
        const float* __restrict__ w1,   // (4,64)
        const float* __restrict__ w2,   // (64,4)
        float* __restrict__ out, int out_size) {
    __shared__ float s_avg[Bq * Cq];
    __shared__ float s_mx[Bq * Cq];
    __shared__ int s_red[256];

    int tid = threadIdx.x;
    // 2 threads per (b,c) row of 1024 partials; float4 over 512 each
    {
        int rc   = tid >> 1;            // 0..127
        int half = tid & 1;
        const float4* ps = (const float4*)(g_sum_b[rc]) + half * 128;
        const float4* pm = (const float4*)(g_max_b[rc]) + half * 128;
        float a = 0.0f, m = -INFINITY;
#pragma unroll 4
        for (int k = 0; k < 128; k++) {
            float4 v = ps[k];
            a += v.x + v.y + v.z + v.w;
            float4 u = pm[k];
            m = fmaxf(m, fmaxf(fmaxf(u.x, u.y), fmaxf(u.z, u.w)));
        }
        a += __shfl_xor_sync(0xffffffffu, a, 1);
        m = fmaxf(m, __shfl_xor_sync(0xffffffffu, m, 1));
        if (half == 0) { s_avg[rc] = a * (1.0f / HWq); s_mx[rc] = m; }
    }
    {
        int t = 0;
#pragma unroll
        for (int k = 0; k < Bq * PBLK / 256; k++) t += g_cnt_blk[tid + k * 256];
        s_red[tid] = t;
    }
    __syncthreads();

    if (tid < Bq * Cq) {
        int b = tid >> 6, c = tid & 63;
        float og = 0.0f;
#pragma unroll
        for (int j = 0; j < 4; j++) {
            float sa = 0.0f, sm = 0.0f;
            for (int cc = 0; cc < Cq; cc++) {
                float w = w1[j * Cq + cc];
                sa += s_avg[b * Cq + cc] * w;
                sm += s_mx[b * Cq + cc] * w;
            }
            og += (fmaxf(sa, 0.0f) + fmaxf(sm, 0.0f)) * w2[c * 4 + j];
        }
        g_gate[tid] = 1.0f / (1.0f + expf(-og));
    }

    for (int st = 128; st > 0; st >>= 1) {
        __syncthreads();
        if (tid < st) s_red[tid] += s_red[tid + st];
    }
    if (tid == 0 && out_size > OUTQ)
        out[OUTQ] = (float)s_red[0] / (float)NHWq;
}

// ============ kernel 3: pure streaming gate apply ============
__global__ void __launch_bounds__(256) scale_kernel(float* __restrict__ out) {
    int cg = blockIdx.x >> 5;             // 1024 floats per block; 32 blocks per channel
    float g = g_gate[cg];
    float4* o4 = (float4*)out + (size_t)blockIdx.x * 256 + threadIdx.x;
    float4 v = *o4;
    v.x *= g; v.y *= g; v.z *= g; v.w *= g;
    *o4 = v;
}

// ---------------- launch ----------------
extern "C" void kernel_launch(void* const* d_in, const int* in_sizes, int n_in,
                              void* d_out, int out_size) {
    const float* x         = (const float*)d_in[0];
    const float* psm       = (const float*)d_in[1];
    const float* inv_delay = (const float*)d_in[2];
    const float* ew_w      = (const float*)d_in[3];
    const float* ew_b      = (const float*)d_in[4];
    const float* ewc_w     = (const float*)d_in[5];
    const float* ewc_b     = (const float*)d_in[6];
    const float* sta_w1    = (const float*)d_in[7];
    const float* sta_w2    = (const float*)d_in[8];
    float* out = (float*)d_out;

    dim3 gf(PBLK, Bq);
    fuse_kernel<<<gf, 256>>>(x, psm, inv_delay, ew_w, ew_b, ewc_w, ewc_b, out);
    reduce_gate_kernel<<<1, 256>>>(sta_w1, sta_w2, out, out_size);
    scale_kernel<<<OUTQ / 1024, 256>>>(out);
}

// round 12
// speedup vs baseline: 1.7742x; 1.7742x over previous
#include <cuda_runtime.h>
#include <math.h>

#define Bq 2
#define Lq 5
#define Nq 10
#define Cq 64
#define Hq 128
#define Wq 256
#define HWq (Hq * Wq)          // 32768
#define NHWq (Nq * HWq)        // 327680
#define OUTQ (Bq * Cq * HWq)   // 4194304

#define MGX (Wq / 64)          // 4
#define MGY (Hq / 8)           // 16
#define MASK_BLOCKS (MGX * MGY * Nq)   // 640

#define NSLOT 64               // pooling replication factor (decontends L2 atomics)

// ---------------- scratch (no allocations allowed) ----------------
__device__ float        g_mask[NHWq];
__device__ float        g_sum_r[NSLOT][Bq * Cq];
__device__ unsigned int g_max_r[NSLOT][Bq * Cq];   // monotonic-encoded float max
__device__ float        g_gate[Bq * Cq];
__device__ int          g_blkcnt[MASK_BLOCKS];

// separable 5-tap Gaussian, sigma=1:  k2d = (1/2pi) * g1[dy] * g1[dx]
__constant__ float GX[5] = {0.13533528f, 0.60653066f, 1.0f, 0.60653066f, 0.13533528f};
__constant__ float GY[5] = {0.13533528f * 0.15915494f, 0.60653066f * 0.15915494f,
                            0.15915494f, 0.60653066f * 0.15915494f, 0.13533528f * 0.15915494f};

__device__ __forceinline__ float fsig(float x) { return 1.0f / (1.0f + __expf(-x)); }

// monotonic float<->uint order-preserving encode (max identity = 0u)
__device__ __forceinline__ unsigned int fenc(float f) {
    unsigned int u = __float_as_uint(f);
    return (u & 0x80000000u) ? ~u : (u | 0x80000000u);
}
__device__ __forceinline__ float fdec(unsigned int e) {
    return __uint_as_float((e & 0x80000000u) ? (e & 0x7FFFFFFFu) : ~e);
}

// ============ kernel 1: conf + separable gaussian + mask (2 px/thread, 64x8 tiles) ============
__global__ void __launch_bounds__(256) conf_mask_kernel(
        const float* __restrict__ psm,
        const float* __restrict__ inv_delay,
        const float* __restrict__ ewc_w,
        const float* __restrict__ ewc_b) {
    const int TX = 64, TY = 8;
    __shared__ float sc[TY + 4][TX + 4];   // 12 x 68 halo tile
    __shared__ float ht[TY + 4][TX];       // 12 x 64 horizontally filtered
    __shared__ int s_cnt;

    int n  = blockIdx.z;
    int w0 = blockIdx.x * TX;
    int h0 = blockIdx.y * TY;
    int tid = threadIdx.x;
    int flat = (n * MGY + blockIdx.y) * MGX + blockIdx.x;

    // re-init replicated pooling scratch each replay (first NSLOT blocks; before fuse via PDL edge)
    if (flat < NSLOT) {
        if (tid < Bq * Cq)            g_sum_r[flat][tid] = 0.0f;
        else if (tid < 2 * Bq * Cq)   g_max_r[flat][tid - Bq * Cq] = 0u;
    }
    if (tid == 0) s_cnt = 0;

    float enc = tanhf(inv_delay[n] * ewc_w[0] + ewc_b[0]) + 1.0f;
    const float* p0 = psm + (size_t)(n * 2 + 0) * HWq;
    const float* p1 = psm + (size_t)(n * 2 + 1) * HWq;

    // stage 1: conf tile with halo (816 elements)
#pragma unroll
    for (int k = 0; k < 4; k++) {
        int i = tid + k * 256;
        if (i < (TY + 4) * (TX + 4)) {
            int sy = i / (TX + 4);
            int sx = i - sy * (TX + 4);
            int h = h0 + sy - 2, w = w0 + sx - 2;
            float v = 0.0f;                               // zero-pad = 'SAME'
            if (h >= 0 && h < Hq && w >= 0 && w < Wq) {
                int idx = h * Wq + w;
                v = fmaxf(fsig(p0[idx]), fsig(p1[idx])) * enc;
            }
            sc[sy][sx] = v;
        }
    }
    __syncthreads();

    // stage 2: horizontal 5-tap (768 elements)
#pragma unroll
    for (int k = 0; k < 3; k++) {
        int i = tid + k * 256;
        int sy = i >> 6, sx = i & 63;
        float a = 0.0f;
#pragma unroll
        for (int d = 0; d < 5; d++) a += GX[d] * sc[sy][sx + d];
        ht[sy][sx] = a;
    }
    __syncthreads();

    // stage 3: vertical 5-tap + threshold + ego + count, 2 px per thread
    int cnt = 0;
#pragma unroll
    for (int k = 0; k < 2; k++) {
        int px = tid + k * 256;
        int ty = px >> 6, tx = px & 63;
        float acc = 0.0f;
#pragma unroll
        for (int d = 0; d < 5; d++) acc += GY[d] * ht[ty + d][tx];
        float m = (acc > 0.01f || n % Lq == 0) ? 1.0f : 0.0f;   // ego always communicates
        g_mask[(size_t)n * HWq + (h0 + ty) * Wq + (w0 + tx)] = m;
        unsigned bal = __ballot_sync(0xffffffffu, m > 0.5f);
        if ((tid & 31) == 0) cnt += __popc(bal);
    }
    if ((tid & 31) == 0) atomicAdd(&s_cnt, cnt);
    __syncthreads();
    if (tid == 0) g_blkcnt[flat] = s_cnt;
    __syncthreads();                       // all stores done in every thread's past
    cudaTriggerProgrammaticLaunchCompletion();
}

// ============ kernel 2: single-pass attention + pooling (R10 shape + PDL early loads) ============
__global__ void __launch_bounds__(256, 4) fuse_kernel(
        const float* __restrict__ x,
        const float* __restrict__ inv_delay,
        const float* __restrict__ ew_w,
        const float* __restrict__ ew_b,
        float* __restrict__ out) {
    __shared__ float s_part[8][Lq][32];
    __shared__ float s_enw[Lq];

    int b    = blockIdx.y;
    int lane = threadIdx.x & 31;
    int wid  = threadIdx.x >> 5;
    int p    = blockIdx.x * 32 + lane;
    int slot = blockIdx.x & (NSLOT - 1);

    if (threadIdx.x < Lq)
        s_enw[threadIdx.x] = tanhf(inv_delay[b * Lq + threadIdx.x] * ew_w[0] + ew_b[0]) + 1.0f;

    // front-issue the 40 x loads (external input, no dependence on conf_mask)
    const float* xb = x + ((size_t)(b * Lq) * Cq + wid * 8) * HWq + p;
    float xv[8][Lq];
#pragma unroll
    for (int c = 0; c < 8; c++)
#pragma unroll
        for (int l = 0; l < Lq; l++)
            xv[c][l] = xb[((size_t)l * Cq + c) * HWq];

    cudaGridDependencySynchronize();       // conf_mask's g_mask / pool-init now visible

    float mk[Lq];
#pragma unroll
    for (int l = 0; l < Lq; l++) mk[l] = g_mask[(size_t)(b * Lq + l) * HWq + p];

    float pd[Lq] = {0.f, 0.f, 0.f, 0.f, 0.f};
#pragma unroll
    for (int c = 0; c < 8; c++) {
        float e = xv[c][0];
#pragma unroll
        for (int l = 0; l < Lq; l++) pd[l] += e * xv[c][l];
    }
#pragma unroll
    for (int l = 0; l < Lq; l++) s_part[wid][l][lane] = pd[l];
    __syncthreads();

    float dot[Lq];
#pragma unroll
    for (int l = 0; l < Lq; l++) {
        float t = 0.0f;
#pragma unroll
        for (int w = 0; w < 8; w++) t += s_part[w][l][lane];
        dot[l] = t;
    }

    float s[Lq];
#pragma unroll
    for (int l = 0; l < Lq; l++) s[l] = s_enw[l] * mk[l];

    float scv[Lq], mx = -INFINITY;
#pragma unroll
    for (int l = 0; l < Lq; l++) {
        scv[l] = dot[l] * s[0] * s[l] * 0.125f;           // 1/sqrt(64)
        mx = fmaxf(mx, scv[l]);
    }
    float esum = 0.0f;
#pragma unroll
    for (int l = 0; l < Lq; l++) { scv[l] = __expf(scv[l] - mx); esum += scv[l]; }
    float inv = 1.0f / esum;
    float coef[Lq];
#pragma unroll
    for (int l = 0; l < Lq; l++) coef[l] = scv[l] * inv * s[l];

    float* ob = out + ((size_t)b * Cq + wid * 8) * HWq + p;
    int cbase = b * Cq + wid * 8;
#pragma unroll
    for (int c = 0; c < 8; c++) {
        float f = 0.0f;
#pragma unroll
        for (int l = 0; l < Lq; l++) f += coef[l] * xv[c][l];
        ob[(size_t)c * HWq] = f;
        float ws = f, wm = f;
#pragma unroll
        for (int o = 16; o > 0; o >>= 1) {
            ws += __shfl_xor_sync(0xffffffffu, ws, o);
            wm = fmaxf(wm, __shfl_xor_sync(0xffffffffu, wm, o));
        }
        if (lane == 0) {
            atomicAdd(&g_sum_r[slot][cbase + c], ws);         // decontended RED.ADD
            atomicMax(&g_max_r[slot][cbase + c], fenc(wm));   // decontended RED.MAX.U32
        }
    }
}

// ============ kernel 3: fold slots + gate MLP + comm_rate (single small block) ============
__global__ void __launch_bounds__(256) reduce_gate_kernel(
        const float* __restrict__ w1,   // (4,64)
        const float* __restrict__ w2,   // (64,4)
        float* __restrict__ out, int out_size) {
    __shared__ float s_avg[Bq * Cq];
    __shared__ float s_mx[Bq * Cq];
    __shared__ int s_red[256];

    int tid = threadIdx.x;

    if (tid < Bq * Cq) {
        float a = 0.0f;
#pragma unroll 8
        for (int s = 0; s < NSLOT; s++) a += g_sum_r[s][tid];
        s_avg[tid] = a * (1.0f / HWq);
    } else {
        int c = tid - Bq * Cq;
        unsigned int e = 0u;
#pragma unroll 8
        for (int s = 0; s < NSLOT; s++) e = max(e, g_max_r[s][c]);
        s_mx[c] = fdec(e);
    }

    int t = 0;
    for (int i = tid; i < MASK_BLOCKS; i += 256) t += g_blkcnt[i];
    s_red[tid] = t;
    __syncthreads();

    if (tid < Bq * Cq) {
        int b = tid >> 6, c = tid & 63;
        float og = 0.0f;
#pragma unroll
        for (int j = 0; j < 4; j++) {
            float sa = 0.0f, sm = 0.0f;
            for (int cc = 0; cc < Cq; cc++) {
                float w = w1[j * Cq + cc];
                sa += s_avg[b * Cq + cc] * w;
                sm += s_mx[b * Cq + cc] * w;
            }
            og += (fmaxf(sa, 0.0f) + fmaxf(sm, 0.0f)) * w2[c * 4 + j];
        }
        g_gate[tid] = 1.0f / (1.0f + expf(-og));
    }
    __syncthreads();                       // gate stores complete
    cudaTriggerProgrammaticLaunchCompletion();

    for (int st = 128; st > 0; st >>= 1) {
        __syncthreads();
        if (tid < st) s_red[tid] += s_red[tid + st];
    }
    if (tid == 0 && out_size > OUTQ)
        out[OUTQ] = (float)s_red[0] / (float)NHWq;     // scale never touches out[OUTQ]
}

// ============ kernel 4: streaming gate apply (PDL: out load issued before gate sync) ============
__global__ void __launch_bounds__(256) scale_kernel(float* __restrict__ out) {
    int cg = blockIdx.x >> 5;             // 1024 floats per block; 32 blocks per channel
    float4* o4 = (float4*)out + (size_t)blockIdx.x * 256 + threadIdx.x;
    float4 v = *o4;                        // independent of reduce_gate
    cudaGridDependencySynchronize();       // g_gate now visible
    float g = g_gate[cg];
    v.x *= g; v.y *= g; v.z *= g; v.w *= g;
    *o4 = v;
}

// ---------------- launch ----------------
extern "C" void kernel_launch(void* const* d_in, const int* in_sizes, int n_in,
                              void* d_out, int out_size) {
    const float* x         = (const float*)d_in[0];
    const float* psm       = (const float*)d_in[1];
    const float* inv_delay = (const float*)d_in[2];
    const float* ew_w      = (const float*)d_in[3];
    const float* ew_b      = (const float*)d_in[4];
    const float* ewc_w     = (const float*)d_in[5];
    const float* ewc_b     = (const float*)d_in[6];
    const float* sta_w1    = (const float*)d_in[7];
    const float* sta_w2    = (const float*)d_in[8];
    float* out = (float*)d_out;

    dim3 gm(MGX, MGY, Nq);
    conf_mask_kernel<<<gm, 256>>>(psm, inv_delay, ewc_w, ewc_b);

    cudaLaunchAttribute pdl[1];
    pdl[0].id = cudaLaunchAttributeProgrammaticStreamSerialization;
    pdl[0].val.programmaticStreamSerializationAllowed = 1;

    {
        cudaLaunchConfig_t cfg = {};
        cfg.gridDim  = dim3(HWq / 32, Bq);
        cfg.blockDim = dim3(256);
        cfg.attrs = pdl; cfg.numAttrs = 1;
        cudaLaunchKernelEx(&cfg, fuse_kernel, x, inv_delay, ew_w, ew_b, out);
    }

    reduce_gate_kernel<<<1, 256>>>(sta_w1, sta_w2, out, out_size);

    {
        cudaLaunchConfig_t cfg = {};
        cfg.gridDim  = dim3(OUTQ / 1024);
        cfg.blockDim = dim3(256);
        cfg.attrs = pdl; cfg.numAttrs = 1;
        cudaLaunchKernelEx(&cfg, scale_kernel, out);
    }
}

// round 13
// speedup vs baseline: 1.7826x; 1.0048x over previous
#include <cuda_runtime.h>
#include <math.h>

#define Bq 2
#define Lq 5
#define Nq 10
#define Cq 64
#define Hq 128
#define Wq 256
#define HWq (Hq * Wq)          // 32768
#define NHWq (Nq * HWq)        // 327680
#define OUTQ (Bq * Cq * HWq)   // 4194304

#define MGX (Wq / 64)          // 4
#define MGY (Hq / 8)           // 16
#define MASK_BLOCKS (MGX * MGY * Nq)   // 640

#define NSLOT 64               // pooling replication factor (decontends L2 atomics)

// ---------------- scratch (no allocations allowed) ----------------
__device__ float        g_mask[NHWq];
__device__ float        g_sum_r[NSLOT][Bq * Cq];
__device__ unsigned int g_max_r[NSLOT][Bq * Cq];   // monotonic-encoded float max
__device__ float        g_gate[Bq * Cq];
__device__ int          g_blkcnt[MASK_BLOCKS];

// separable 5-tap Gaussian, sigma=1:  k2d = (1/2pi) * g1[dy] * g1[dx]
__constant__ float GX[5] = {0.13533528f, 0.60653066f, 1.0f, 0.60653066f, 0.13533528f};
__constant__ float GY[5] = {0.13533528f * 0.15915494f, 0.60653066f * 0.15915494f,
                            0.15915494f, 0.60653066f * 0.15915494f, 0.13533528f * 0.15915494f};

__device__ __forceinline__ float fsig(float x) { return 1.0f / (1.0f + __expf(-x)); }

// monotonic float<->uint order-preserving encode (max identity = 0u)
__device__ __forceinline__ unsigned int fenc(float f) {
    unsigned int u = __float_as_uint(f);
    return (u & 0x80000000u) ? ~u : (u | 0x80000000u);
}
__device__ __forceinline__ float fdec(unsigned int e) {
    return __uint_as_float((e & 0x80000000u) ? (e & 0x7FFFFFFFu) : ~e);
}

// ============ kernel 1: conf + separable gaussian + mask (2 px/thread, 64x8 tiles) ============
__global__ void __launch_bounds__(256) conf_mask_kernel(
        const float* __restrict__ psm,
        const float* __restrict__ inv_delay,
        const float* __restrict__ ewc_w,
        const float* __restrict__ ewc_b) {
    const int TX = 64, TY = 8;
    __shared__ float sc[TY + 4][TX + 4];
    __shared__ float ht[TY + 4][TX];
    __shared__ int s_cnt;

    int n  = blockIdx.z;
    int w0 = blockIdx.x * TX;
    int h0 = blockIdx.y * TY;
    int tid = threadIdx.x;
    int flat = (n * MGY + blockIdx.y) * MGX + blockIdx.x;

    if (flat < NSLOT) {
        if (tid < Bq * Cq)            g_sum_r[flat][tid] = 0.0f;
        else if (tid < 2 * Bq * Cq)   g_max_r[flat][tid - Bq * Cq] = 0u;
    }
    if (tid == 0) s_cnt = 0;

    float enc = tanhf(inv_delay[n] * ewc_w[0] + ewc_b[0]) + 1.0f;
    const float* p0 = psm + (size_t)(n * 2 + 0) * HWq;
    const float* p1 = psm + (size_t)(n * 2 + 1) * HWq;

#pragma unroll
    for (int k = 0; k < 4; k++) {
        int i = tid + k * 256;
        if (i < (TY + 4) * (TX + 4)) {
            int sy = i / (TX + 4);
            int sx = i - sy * (TX + 4);
            int h = h0 + sy - 2, w = w0 + sx - 2;
            float v = 0.0f;                               // zero-pad = 'SAME'
            if (h >= 0 && h < Hq && w >= 0 && w < Wq) {
                int idx = h * Wq + w;
                v = fmaxf(fsig(p0[idx]), fsig(p1[idx])) * enc;
            }
            sc[sy][sx] = v;
        }
    }
    __syncthreads();

#pragma unroll
    for (int k = 0; k < 3; k++) {
        int i = tid + k * 256;
        int sy = i >> 6, sx = i & 63;
        float a = 0.0f;
#pragma unroll
        for (int d = 0; d < 5; d++) a += GX[d] * sc[sy][sx + d];
        ht[sy][sx] = a;
    }
    __syncthreads();

    int cnt = 0;
#pragma unroll
    for (int k = 0; k < 2; k++) {
        int px = tid + k * 256;
        int ty = px >> 6, tx = px & 63;
        float acc = 0.0f;
#pragma unroll
        for (int d = 0; d < 5; d++) acc += GY[d] * ht[ty + d][tx];
        float m = (acc > 0.01f || n % Lq == 0) ? 1.0f : 0.0f;   // ego always communicates
        g_mask[(size_t)n * HWq + (h0 + ty) * Wq + (w0 + tx)] = m;
        unsigned bal = __ballot_sync(0xffffffffu, m > 0.5f);
        if ((tid & 31) == 0) cnt += __popc(bal);
    }
    if ((tid & 31) == 0) atomicAdd(&s_cnt, cnt);
    __syncthreads();
    if (tid == 0) g_blkcnt[flat] = s_cnt;
    __syncthreads();
    cudaTriggerProgrammaticLaunchCompletion();
}

// ============ kernel 2: attention + pooling, float2-vectorized (64 px/block) ============
// 8 warps; warp w owns channels [8w,8w+8); lane owns a PIXEL PAIR -> all x traffic via LDG.64.
__global__ void __launch_bounds__(256, 2) fuse_kernel(
        const float* __restrict__ x,
        const float* __restrict__ inv_delay,
        const float* __restrict__ ew_w,
        const float* __restrict__ ew_b,
        float* __restrict__ out) {
    __shared__ float2 s_part[8][Lq][32];
    __shared__ float s_enw[Lq];

    int b    = blockIdx.y;
    int lane = threadIdx.x & 31;
    int wid  = threadIdx.x >> 5;
    int pp   = blockIdx.x * 32 + lane;       // float2 index: pixels {2pp, 2pp+1}
    int slot = blockIdx.x & (NSLOT - 1);

    if (threadIdx.x < Lq)
        s_enw[threadIdx.x] = tanhf(inv_delay[b * Lq + threadIdx.x] * ew_w[0] + ew_b[0]) + 1.0f;

    // front-issue the 40 LDG.64 x loads (no dependence on conf_mask)
    const float2* xb = (const float2*)(x + ((size_t)(b * Lq) * Cq + wid * 8) * HWq) + pp;
    float2 xv[8][Lq];
#pragma unroll
    for (int c = 0; c < 8; c++)
#pragma unroll
        for (int l = 0; l < Lq; l++)
            xv[c][l] = xb[((size_t)l * Cq + c) * (HWq / 2)];

    cudaGridDependencySynchronize();         // g_mask / pool-init now visible

    float2 mk[Lq];
#pragma unroll
    for (int l = 0; l < Lq; l++)
        mk[l] = ((const float2*)(g_mask + (size_t)(b * Lq + l) * HWq))[pp];

    float2 pd[Lq];
#pragma unroll
    for (int l = 0; l < Lq; l++) pd[l] = make_float2(0.0f, 0.0f);
#pragma unroll
    for (int c = 0; c < 8; c++) {
        float2 e = xv[c][0];
#pragma unroll
        for (int l = 0; l < Lq; l++) {
            pd[l].x += e.x * xv[c][l].x;
            pd[l].y += e.y * xv[c][l].y;
        }
    }
#pragma unroll
    for (int l = 0; l < Lq; l++) s_part[wid][l][lane] = pd[l];
    __syncthreads();

    float2 dot[Lq];
#pragma unroll
    for (int l = 0; l < Lq; l++) {
        float tx = 0.0f, ty = 0.0f;
#pragma unroll
        for (int w = 0; w < 8; w++) {
            float2 v = s_part[w][l][lane];
            tx += v.x; ty += v.y;
        }
        dot[l] = make_float2(tx, ty);
    }

    float2 s[Lq];
#pragma unroll
    for (int l = 0; l < Lq; l++) {
        s[l].x = s_enw[l] * mk[l].x;
        s[l].y = s_enw[l] * mk[l].y;
    }

    float2 coef[Lq];
    {
        float scv[Lq], mx = -INFINITY;
#pragma unroll
        for (int l = 0; l < Lq; l++) {
            scv[l] = dot[l].x * s[0].x * s[l].x * 0.125f;   // 1/sqrt(64)
            mx = fmaxf(mx, scv[l]);
        }
        float es = 0.0f;
#pragma unroll
        for (int l = 0; l < Lq; l++) { scv[l] = __expf(scv[l] - mx); es += scv[l]; }
        float inv = 1.0f / es;
#pragma unroll
        for (int l = 0; l < Lq; l++) coef[l].x = scv[l] * inv * s[l].x;
    }
    {
        float scv[Lq], mx = -INFINITY;
#pragma unroll
        for (int l = 0; l < Lq; l++) {
            scv[l] = dot[l].y * s[0].y * s[l].y * 0.125f;
            mx = fmaxf(mx, scv[l]);
        }
        float es = 0.0f;
#pragma unroll
        for (int l = 0; l < Lq; l++) { scv[l] = __expf(scv[l] - mx); es += scv[l]; }
        float inv = 1.0f / es;
#pragma unroll
        for (int l = 0; l < Lq; l++) coef[l].y = scv[l] * inv * s[l].y;
    }

    float2* ob = (float2*)(out + ((size_t)b * Cq + wid * 8) * HWq) + pp;
    int cbase = b * Cq + wid * 8;
#pragma unroll
    for (int c = 0; c < 8; c++) {
        float fx = 0.0f, fy = 0.0f;
#pragma unroll
        for (int l = 0; l < Lq; l++) {
            fx += coef[l].x * xv[c][l].x;
            fy += coef[l].y * xv[c][l].y;
        }
        ob[(size_t)c * (HWq / 2)] = make_float2(fx, fy);
        float ws = fx + fy;
        float wm = fmaxf(fx, fy);
#pragma unroll
        for (int o = 16; o > 0; o >>= 1) {
            ws += __shfl_xor_sync(0xffffffffu, ws, o);
            wm = fmaxf(wm, __shfl_xor_sync(0xffffffffu, wm, o));
        }
        if (lane == 0) {
            atomicAdd(&g_sum_r[slot][cbase + c], ws);         // decontended RED.ADD
            atomicMax(&g_max_r[slot][cbase + c], fenc(wm));   // decontended RED.MAX.U32
        }
    }
}

// ============ kernel 3: fold slots + gate MLP + comm_rate (single small block) ============
__global__ void __launch_bounds__(256) reduce_gate_kernel(
        const float* __restrict__ w1,   // (4,64)
        const float* __restrict__ w2,   // (64,4)
        float* __restrict__ out, int out_size) {
    __shared__ float s_avg[Bq * Cq];
    __shared__ float s_mx[Bq * Cq];
    __shared__ int s_red[256];

    int tid = threadIdx.x;

    if (tid < Bq * Cq) {
        float a = 0.0f;
#pragma unroll 8
        for (int s = 0; s < NSLOT; s++) a += g_sum_r[s][tid];
        s_avg[tid] = a * (1.0f / HWq);
    } else {
        int c = tid - Bq * Cq;
        unsigned int e = 0u;
#pragma unroll 8
        for (int s = 0; s < NSLOT; s++) e = max(e, g_max_r[s][c]);
        s_mx[c] = fdec(e);
    }

    int t = 0;
    for (int i = tid; i < MASK_BLOCKS; i += 256) t += g_blkcnt[i];
    s_red[tid] = t;
    __syncthreads();

    if (tid < Bq * Cq) {
        int b = tid >> 6, c = tid & 63;
        float og = 0.0f;
#pragma unroll
        for (int j = 0; j < 4; j++) {
            float sa = 0.0f, sm = 0.0f;
            for (int cc = 0; cc < Cq; cc++) {
                float w = w1[j * Cq + cc];
                sa += s_avg[b * Cq + cc] * w;
                sm += s_mx[b * Cq + cc] * w;
            }
            og += (fmaxf(sa, 0.0f) + fmaxf(sm, 0.0f)) * w2[c * 4 + j];
        }
        g_gate[tid] = 1.0f / (1.0f + expf(-og));
    }
    __syncthreads();                       // gate stores complete
    cudaTriggerProgrammaticLaunchCompletion();

    for (int st = 128; st > 0; st >>= 1) {
        __syncthreads();
        if (tid < st) s_red[tid] += s_red[tid + st];
    }
    if (tid == 0 && out_size > OUTQ)
        out[OUTQ] = (float)s_red[0] / (float)NHWq;     // scale never touches out[OUTQ]
}

// ============ kernel 4: streaming gate apply (PDL early load) ============
__global__ void __launch_bounds__(256) scale_kernel(float* __restrict__ out) {
    int cg = blockIdx.x >> 5;             // 1024 floats per block; 32 blocks per channel
    float4* o4 = (float4*)out + (size_t)blockIdx.x * 256 + threadIdx.x;
    float4 v = *o4;                        // independent of reduce_gate
    cudaGridDependencySynchronize();       // g_gate now visible
    float g = g_gate[cg];
    v.x *= g; v.y *= g; v.z *= g; v.w *= g;
    *o4 = v;
}

// ---------------- launch ----------------
extern "C" void kernel_launch(void* const* d_in, const int* in_sizes, int n_in,
                              void* d_out, int out_size) {
    const float* x         = (const float*)d_in[0];
    const float* psm       = (const float*)d_in[1];
    const float* inv_delay = (const float*)d_in[2];
    const float* ew_w      = (const float*)d_in[3];
    const float* ew_b      = (const float*)d_in[4];
    const float* ewc_w     = (const float*)d_in[5];
    const float* ewc_b     = (const float*)d_in[6];
    const float* sta_w1    = (const float*)d_in[7];
    const float* sta_w2    = (const float*)d_in[8];
    float* out = (float*)d_out;

    dim3 gm(MGX, MGY, Nq);
    conf_mask_kernel<<<gm, 256>>>(psm, inv_delay, ewc_w, ewc_b);

    cudaLaunchAttribute pdl[1];
    pdl[0].id = cudaLaunchAttributeProgrammaticStreamSerialization;
    pdl[0].val.programmaticStreamSerializationAllowed = 1;

    {
        cudaLaunchConfig_t cfg = {};
        cfg.gridDim  = dim3(HWq / 64, Bq);
        cfg.blockDim = dim3(256);
        cfg.attrs = pdl; cfg.numAttrs = 1;
        cudaLaunchKernelEx(&cfg, fuse_kernel, x, inv_delay, ew_w, ew_b, out);
    }

    reduce_gate_kernel<<<1, 256>>>(sta_w1, sta_w2, out, out_size);

    {
        cudaLaunchConfig_t cfg = {};
        cfg.gridDim  = dim3(OUTQ / 1024);
        cfg.blockDim = dim3(256);
        cfg.attrs = pdl; cfg.numAttrs = 1;
        cudaLaunchKernelEx(&cfg, scale_kernel, out);
    }
}

// round 14
// speedup vs baseline: 1.9524x; 1.0952x over previous
#include <cuda_runtime.h>
#include <math.h>

#define Bq 2
#define Lq 5
#define Nq 10
#define Cq 64
#define Hq 128
#define Wq 256
#define HWq (Hq * Wq)          // 32768
#define NHWq (Nq * HWq)        // 327680
#define OUTQ (Bq * Cq * HWq)   // 4194304

#define MGX (Wq / 64)          // 4
#define MGY (Hq / 8)           // 16
#define MASK_BLOCKS (MGX * MGY * Nq)   // 640

#define NSLOT 64               // pooling replication factor (decontends L2 atomics)

// ---------------- scratch (no allocations allowed) ----------------
__device__ float        g_mask[NHWq];
__device__ float        g_sum_r[NSLOT][Bq * Cq];
__device__ unsigned int g_max_r[NSLOT][Bq * Cq];   // monotonic-encoded float max
__device__ float        g_gate[Bq * Cq];
__device__ int          g_blkcnt[MASK_BLOCKS];

// separable 5-tap Gaussian, sigma=1:  k2d = (1/2pi) * g1[dy] * g1[dx]
__constant__ float GX[5] = {0.13533528f, 0.60653066f, 1.0f, 0.60653066f, 0.13533528f};
__constant__ float GY[5] = {0.13533528f * 0.15915494f, 0.60653066f * 0.15915494f,
                            0.15915494f, 0.60653066f * 0.15915494f, 0.13533528f * 0.15915494f};

__device__ __forceinline__ float fsig(float x) { return 1.0f / (1.0f + __expf(-x)); }

// monotonic float<->uint order-preserving encode (max identity = 0u)
__device__ __forceinline__ unsigned int fenc(float f) {
    unsigned int u = __float_as_uint(f);
    return (u & 0x80000000u) ? ~u : (u | 0x80000000u);
}
__device__ __forceinline__ float fdec(unsigned int e) {
    return __uint_as_float((e & 0x80000000u) ? (e & 0x7FFFFFFFu) : ~e);
}

// ============ kernel 1: conf + separable gaussian + mask (2 px/thread, 64x8 tiles) ============
__global__ void __launch_bounds__(256) conf_mask_kernel(
        const float* __restrict__ psm,
        const float* __restrict__ inv_delay,
        const float* __restrict__ ewc_w,
        const float* __restrict__ ewc_b) {
    const int TX = 64, TY = 8;
    __shared__ float sc[TY + 4][TX + 4];
    __shared__ float ht[TY + 4][TX];
    __shared__ int s_cnt;

    int n  = blockIdx.z;
    int w0 = blockIdx.x * TX;
    int h0 = blockIdx.y * TY;
    int tid = threadIdx.x;
    int flat = (n * MGY + blockIdx.y) * MGX + blockIdx.x;

    if (flat < NSLOT) {
        if (tid < Bq * Cq)            g_sum_r[flat][tid] = 0.0f;
        else if (tid < 2 * Bq * Cq)   g_max_r[flat][tid - Bq * Cq] = 0u;
    }
    if (tid == 0) s_cnt = 0;

    float enc = tanhf(inv_delay[n] * ewc_w[0] + ewc_b[0]) + 1.0f;
    const float* p0 = psm + (size_t)(n * 2 + 0) * HWq;
    const float* p1 = psm + (size_t)(n * 2 + 1) * HWq;

#pragma unroll
    for (int k = 0; k < 4; k++) {
        int i = tid + k * 256;
        if (i < (TY + 4) * (TX + 4)) {
            int sy = i / (TX + 4);
            int sx = i - sy * (TX + 4);
            int h = h0 + sy - 2, w = w0 + sx - 2;
            float v = 0.0f;                               // zero-pad = 'SAME'
            if (h >= 0 && h < Hq && w >= 0 && w < Wq) {
                int idx = h * Wq + w;
                v = fmaxf(fsig(p0[idx]), fsig(p1[idx])) * enc;
            }
            sc[sy][sx] = v;
        }
    }
    __syncthreads();

#pragma unroll
    for (int k = 0; k < 3; k++) {
        int i = tid + k * 256;
        int sy = i >> 6, sx = i & 63;
        float a = 0.0f;
#pragma unroll
        for (int d = 0; d < 5; d++) a += GX[d] * sc[sy][sx + d];
        ht[sy][sx] = a;
    }
    __syncthreads();

    int cnt = 0;
#pragma unroll
    for (int k = 0; k < 2; k++) {
        int px = tid + k * 256;
        int ty = px >> 6, tx = px & 63;
        float acc = 0.0f;
#pragma unroll
        for (int d = 0; d < 5; d++) acc += GY[d] * ht[ty + d][tx];
        float m = (acc > 0.01f || n % Lq == 0) ? 1.0f : 0.0f;   // ego always communicates
        g_mask[(size_t)n * HWq + (h0 + ty) * Wq + (w0 + tx)] = m;
        unsigned bal = __ballot_sync(0xffffffffu, m > 0.5f);
        if ((tid & 31) == 0) cnt += __popc(bal);
    }
    if ((tid & 31) == 0) atomicAdd(&s_cnt, cnt);
    __syncthreads();
    if (tid == 0) g_blkcnt[flat] = s_cnt;
    __syncthreads();
    cudaTriggerProgrammaticLaunchCompletion();
}

// ============ kernel 2: attention + pooling, float2 + smem fan-ins (instruction diet) ============
// 8 warps; warp w owns channels [8w,8w+8); lane owns a pixel pair (LDG.64 throughout).
__global__ void __launch_bounds__(256, 2) fuse_kernel(
        const float* __restrict__ x,
        const float* __restrict__ inv_delay,
        const float* __restrict__ ew_w,
        const float* __restrict__ ew_b,
        float* __restrict__ out) {
    __shared__ float2 s_buf[8][8][32];     // dots: [w][l<5][lane]; pooling: [w][c][lane]
    __shared__ float2 s_dot[Lq][32];
    __shared__ float s_enw[Lq];

    int b    = blockIdx.y;
    int lane = threadIdx.x & 31;
    int wid  = threadIdx.x >> 5;
    int pp   = blockIdx.x * 32 + lane;       // float2 index: pixels {2pp, 2pp+1}
    int slot = blockIdx.x & (NSLOT - 1);

    if (threadIdx.x < Lq)
        s_enw[threadIdx.x] = tanhf(inv_delay[b * Lq + threadIdx.x] * ew_w[0] + ew_b[0]) + 1.0f;

    // front-issue the 40 LDG.64 x loads (no dependence on conf_mask)
    const float2* xb = (const float2*)(x + ((size_t)(b * Lq) * Cq + wid * 8) * HWq) + pp;
    float2 xv[8][Lq];
#pragma unroll
    for (int c = 0; c < 8; c++)
#pragma unroll
        for (int l = 0; l < Lq; l++)
            xv[c][l] = xb[((size_t)l * Cq + c) * (HWq / 2)];

    cudaGridDependencySynchronize();         // g_mask / pool-init now visible

    float2 mk[Lq];
#pragma unroll
    for (int l = 0; l < Lq; l++)
        mk[l] = ((const float2*)(g_mask + (size_t)(b * Lq + l) * HWq))[pp];

    float2 pd[Lq];
#pragma unroll
    for (int l = 0; l < Lq; l++) pd[l] = make_float2(0.0f, 0.0f);
#pragma unroll
    for (int c = 0; c < 8; c++) {
        float2 e = xv[c][0];
#pragma unroll
        for (int l = 0; l < Lq; l++) {
            pd[l].x += e.x * xv[c][l].x;
            pd[l].y += e.y * xv[c][l].y;
        }
    }
#pragma unroll
    for (int l = 0; l < Lq; l++) s_buf[wid][l][lane] = pd[l];
    __syncthreads();

    // dot fan-in by 160-thread subset (saves 8x redundant LDS walks)
    if (threadIdx.x < Lq * 32) {
        int l = threadIdx.x >> 5, ln = threadIdx.x & 31;
        float tx = 0.0f, ty = 0.0f;
#pragma unroll
        for (int w = 0; w < 8; w++) {
            float2 v = s_buf[w][l][ln];
            tx += v.x; ty += v.y;
        }
        s_dot[l][ln] = make_float2(tx, ty);
    }
    __syncthreads();

    float2 s[Lq];
#pragma unroll
    for (int l = 0; l < Lq; l++) {
        s[l].x = s_enw[l] * mk[l].x;
        s[l].y = s_enw[l] * mk[l].y;
    }

    float2 coef[Lq];
    {
        float scv[Lq], mx = -INFINITY;
#pragma unroll
        for (int l = 0; l < Lq; l++) {
            scv[l] = s_dot[l][lane].x * s[0].x * s[l].x * 0.125f;   // 1/sqrt(64)
            mx = fmaxf(mx, scv[l]);
        }
        float es = 0.0f;
#pragma unroll
        for (int l = 0; l < Lq; l++) { scv[l] = __expf(scv[l] - mx); es += scv[l]; }
        float inv = 1.0f / es;
#pragma unroll
        for (int l = 0; l < Lq; l++) coef[l].x = scv[l] * inv * s[l].x;
    }
    {
        float scv[Lq], mx = -INFINITY;
#pragma unroll
        for (int l = 0; l < Lq; l++) {
            scv[l] = s_dot[l][lane].y * s[0].y * s[l].y * 0.125f;
            mx = fmaxf(mx, scv[l]);
        }
        float es = 0.0f;
#pragma unroll
        for (int l = 0; l < Lq; l++) { scv[l] = __expf(scv[l] - mx); es += scv[l]; }
        float inv = 1.0f / es;
#pragma unroll
        for (int l = 0; l < Lq; l++) coef[l].y = scv[l] * inv * s[l].y;
    }

    // outputs -> gmem; per-channel values -> smem for cooperative pooling
    float2* ob = (float2*)(out + ((size_t)b * Cq + wid * 8) * HWq) + pp;
#pragma unroll
    for (int c = 0; c < 8; c++) {
        float fx = 0.0f, fy = 0.0f;
#pragma unroll
        for (int l = 0; l < Lq; l++) {
            fx += coef[l].x * xv[c][l].x;
            fy += coef[l].y * xv[c][l].y;
        }
        ob[(size_t)c * (HWq / 2)] = make_float2(fx, fy);
        s_buf[wid][c][lane] = make_float2(fx, fy);
    }
    __syncthreads();

    // pooling fan-in: 4 threads per (w,c) pair; each sums 8 lanes, 2-level shuffle combine
    {
        int pair = threadIdx.x >> 2;          // 0..63 = w*8+c
        int sub  = threadIdx.x & 3;
        int w = pair >> 3, c = pair & 7;
        float a = 0.0f, m = -INFINITY;
#pragma unroll
        for (int k = 0; k < 8; k++) {
            float2 v = s_buf[w][c][sub * 8 + k];
            a += v.x + v.y;
            m = fmaxf(m, fmaxf(v.x, v.y));
        }
        a += __shfl_xor_sync(0xffffffffu, a, 1);
        m = fmaxf(m, __shfl_xor_sync(0xffffffffu, m, 1));
        a += __shfl_xor_sync(0xffffffffu, a, 2);
        m = fmaxf(m, __shfl_xor_sync(0xffffffffu, m, 2));
        if (sub == 0) {
            int cb = b * Cq + w * 8 + c;
            atomicAdd(&g_sum_r[slot][cb], a);         // decontended RED.ADD
            atomicMax(&g_max_r[slot][cb], fenc(m));   // decontended RED.MAX.U32
        }
    }
}

// ============ kernel 3: fold slots + gate MLP + comm_rate (single small block) ============
__global__ void __launch_bounds__(256) reduce_gate_kernel(
        const float* __restrict__ w1,   // (4,64)
        const float* __restrict__ w2,   // (64,4)
        float* __restrict__ out, int out_size) {
    __shared__ float s_avg[Bq * Cq];
    __shared__ float s_mx[Bq * Cq];
    __shared__ int s_red[256];

    int tid = threadIdx.x;

    if (tid < Bq * Cq) {
        float a = 0.0f;
#pragma unroll 8
        for (int s = 0; s < NSLOT; s++) a += g_sum_r[s][tid];
        s_avg[tid] = a * (1.0f / HWq);
    } else {
        int c = tid - Bq * Cq;
        unsigned int e = 0u;
#pragma unroll 8
        for (int s = 0; s < NSLOT; s++) e = max(e, g_max_r[s][c]);
        s_mx[c] = fdec(e);
    }

    int t = 0;
    for (int i = tid; i < MASK_BLOCKS; i += 256) t += g_blkcnt[i];
    s_red[tid] = t;
    __syncthreads();

    if (tid < Bq * Cq) {
        int b = tid >> 6, c = tid & 63;
        float og = 0.0f;
#pragma unroll
        for (int j = 0; j < 4; j++) {
            float sa = 0.0f, sm = 0.0f;
            for (int cc = 0; cc < Cq; cc++) {
                float w = w1[j * Cq + cc];
                sa += s_avg[b * Cq + cc] * w;
                sm += s_mx[b * Cq + cc] * w;
            }
            og += (fmaxf(sa, 0.0f) + fmaxf(sm, 0.0f)) * w2[c * 4 + j];
        }
        g_gate[tid] = 1.0f / (1.0f + expf(-og));
    }
    __syncthreads();                       // gate stores complete
    cudaTriggerProgrammaticLaunchCompletion();

    for (int st = 128; st > 0; st >>= 1) {
        __syncthreads();
        if (tid < st) s_red[tid] += s_red[tid + st];
    }
    if (tid == 0 && out_size > OUTQ)
        out[OUTQ] = (float)s_red[0] / (float)NHWq;     // scale never touches out[OUTQ]
}

// ============ kernel 4: streaming gate apply (PDL early load) ============
__global__ void __launch_bounds__(256) scale_kernel(float* __restrict__ out) {
    int cg = blockIdx.x >> 5;             // 1024 floats per block; 32 blocks per channel
    float4* o4 = (float4*)out + (size_t)blockIdx.x * 256 + threadIdx.x;
    float4 v = *o4;                        // independent of reduce_gate
    cudaGridDependencySynchronize();       // g_gate now visible
    float g = g_gate[cg];
    v.x *= g; v.y *= g; v.z *= g; v.w *= g;
    *o4 = v;
}

// ---------------- launch ----------------
extern "C" void kernel_launch(void* const* d_in, const int* in_sizes, int n_in,
                              void* d_out, int out_size) {
    const float* x         = (const float*)d_in[0];
    const float* psm       = (const float*)d_in[1];
    const float* inv_delay = (const float*)d_in[2];
    const float* ew_w      = (const float*)d_in[3];
    const float* ew_b      = (const float*)d_in[4];
    const float* ewc_w     = (const float*)d_in[5];
    const float* ewc_b     = (const float*)d_in[6];
    const float* sta_w1    = (const float*)d_in[7];
    const float* sta_w2    = (const float*)d_in[8];
    float* out = (float*)d_out;

    dim3 gm(MGX, MGY, Nq);
    conf_mask_kernel<<<gm, 256>>>(psm, inv_delay, ewc_w, ewc_b);

    cudaLaunchAttribute pdl[1];
    pdl[0].id = cudaLaunchAttributeProgrammaticStreamSerialization;
    pdl[0].val.programmaticStreamSerializationAllowed = 1;

    {
        cudaLaunchConfig_t cfg = {};
        cfg.gridDim  = dim3(HWq / 64, Bq);
        cfg.blockDim = dim3(256);
        cfg.attrs = pdl; cfg.numAttrs = 1;
        cudaLaunchKernelEx(&cfg, fuse_kernel, x, inv_delay, ew_w, ew_b, out);
    }

    reduce_gate_kernel<<<1, 256>>>(sta_w1, sta_w2, out, out_size);

    {
        cudaLaunchConfig_t cfg = {};
        cfg.gridDim  = dim3(OUTQ / 1024);
        cfg.blockDim = dim3(256);
        cfg.attrs = pdl; cfg.numAttrs = 1;
        cudaLaunchKernelEx(&cfg, scale_kernel, out);
    }
}